// round 1
// baseline (speedup 1.0000x reference)
#include <cuda_runtime.h>
#include <cuda_bf16.h>
#include <cstdint>

// ---------------------------------------------------------------------------
// GAT 2-layer (PyG GATConv semantics) on GB300.
// Pipeline (all graph-capturable, no allocations):
//   detect edge dtype -> decode edges -> CSR build (deg/scan/scatter)
//   -> GEMM1 (x@W1) -> att dots -> per-dst-warp aggregate (softmax w/o max)
//   -> GEMM2 (+att dots fused) -> per-dst-warp aggregate + log_softmax
// ---------------------------------------------------------------------------

#define N_MAX 100000
#define E_MAX 1600000
#define T_MAX (E_MAX + N_MAX)
#define SCAN_B 1024
#define NBLK_SCAN_MAX 128

// scratch (device globals: allocation-free)
__device__ float g_h1[N_MAX * 64];       // layer1 transformed features
__device__ float g_as1[N_MAX * 8];
__device__ float g_ad1[N_MAX * 8];
__device__ float g_hmid[N_MAX * 64];     // elu output of layer 1
__device__ float g_h2[N_MAX * 16];
__device__ float g_as2[N_MAX];
__device__ float g_ad2[N_MAX];
__device__ int   g_src[E_MAX];
__device__ int   g_dst[E_MAX];
__device__ int   g_deg[N_MAX];
__device__ int   g_off[N_MAX + 1];
__device__ int   g_cur[N_MAX];
__device__ int   g_csr[T_MAX];
__device__ int   g_bsum[NBLK_SCAN_MAX];
__device__ int   g_is64;

// ---------------- edge dtype detect + decode ----------------
__global__ void k_detect(const unsigned int* __restrict__ w) {
    // If int64 little-endian with values < 2^31, every odd 32-bit word is 0.
    __shared__ int cnt;
    if (threadIdx.x == 0) cnt = 0;
    __syncthreads();
    int z = 0;
    for (int i = threadIdx.x; i < 2048; i += blockDim.x)
        if (w[2 * i + 1] == 0u) z++;
    atomicAdd(&cnt, z);
    __syncthreads();
    if (threadIdx.x == 0) g_is64 = (cnt > 1024) ? 1 : 0;
}

__global__ void k_decode(const void* __restrict__ ei, int E) {
    int e = blockIdx.x * blockDim.x + threadIdx.x;
    if (e >= E) return;
    int s, d;
    if (g_is64) {
        const long long* p = (const long long*)ei;
        s = (int)p[e];
        d = (int)p[e + E];
    } else {
        const int* p = (const int*)ei;
        s = p[e];
        d = p[e + E];
    }
    g_src[e] = s;
    g_dst[e] = d;
}

// ---------------- CSR build ----------------
__global__ void k_deginit(int N) {
    int i = blockIdx.x * blockDim.x + threadIdx.x;
    if (i < N) g_deg[i] = 1;  // self loop
}
__global__ void k_degcount(int E) {
    int e = blockIdx.x * blockDim.x + threadIdx.x;
    if (e < E) atomicAdd(&g_deg[g_dst[e]], 1);
}
__global__ void k_scan1(int N) {
    __shared__ int s[SCAN_B];
    int i = blockIdx.x * SCAN_B + threadIdx.x;
    int v = (i < N) ? g_deg[i] : 0;
    s[threadIdx.x] = v;
    __syncthreads();
    for (int off = 1; off < SCAN_B; off <<= 1) {
        int t = 0;
        if ((int)threadIdx.x >= off) t = s[threadIdx.x - off];
        __syncthreads();
        s[threadIdx.x] += t;
        __syncthreads();
    }
    if (i < N) g_off[i] = s[threadIdx.x] - v;  // block-local exclusive
    if (threadIdx.x == SCAN_B - 1) g_bsum[blockIdx.x] = s[threadIdx.x];
}
__global__ void k_scan2(int nblk, int N) {
    if (threadIdx.x == 0) {
        int run = 0;
        for (int b = 0; b < nblk; b++) {
            int t = g_bsum[b];
            g_bsum[b] = run;
            run += t;
        }
        g_off[N] = run;
    }
}
__global__ void k_scan3(int N) {
    int i = blockIdx.x * blockDim.x + threadIdx.x;
    if (i < N) {
        int o = g_off[i] + g_bsum[i / SCAN_B];
        g_off[i] = o;
        g_cur[i] = o;
    }
}
__global__ void k_scat_self(int N) {
    int n = blockIdx.x * blockDim.x + threadIdx.x;
    if (n < N) g_csr[atomicAdd(&g_cur[n], 1)] = n;
}
__global__ void k_scat_edge(int E) {
    int e = blockIdx.x * blockDim.x + threadIdx.x;
    if (e < E) g_csr[atomicAdd(&g_cur[g_dst[e]], 1)] = g_src[e];
}

// ---------------- GEMM1: h1 = x @ W1  ([N,128] x [128,64]) ----------------
// block: 256 threads, 32 rows/block. smem: W1 (32KB) + x^T tile (16KB) = 48KB.
__global__ void k_gemm1(const float* __restrict__ x, const float* __restrict__ W,
                        int N) {
    __shared__ float sW[128 * 64];
    __shared__ float sX[128 * 32];  // sX[k*32 + r]
    int tid = threadIdx.x;
    const float4* W4 = (const float4*)W;
    float4* sW4 = (float4*)sW;
#pragma unroll
    for (int i = tid; i < 2048; i += 256) sW4[i] = W4[i];
    int rowbase = blockIdx.x * 32;
    for (int i = tid; i < 1024; i += 256) {
        int r = i >> 5;
        int kq = i & 31;
        int row = rowbase + r;
        float4 v = make_float4(0.f, 0.f, 0.f, 0.f);
        if (row < N) v = *(const float4*)&x[(size_t)row * 128 + kq * 4];
        sX[(kq * 4 + 0) * 32 + r] = v.x;
        sX[(kq * 4 + 1) * 32 + r] = v.y;
        sX[(kq * 4 + 2) * 32 + r] = v.z;
        sX[(kq * 4 + 3) * 32 + r] = v.w;
    }
    __syncthreads();
    int cg = tid & 15;   // 4 cols each
    int rg = tid >> 4;   // 2 rows each
    int r0 = rg * 2;
    float a00 = 0, a01 = 0, a02 = 0, a03 = 0;
    float a10 = 0, a11 = 0, a12 = 0, a13 = 0;
#pragma unroll 8
    for (int k = 0; k < 128; k++) {
        float4 w = *(const float4*)&sW[k * 64 + cg * 4];
        float x0 = sX[k * 32 + r0];
        float x1 = sX[k * 32 + r0 + 1];
        a00 = fmaf(x0, w.x, a00); a01 = fmaf(x0, w.y, a01);
        a02 = fmaf(x0, w.z, a02); a03 = fmaf(x0, w.w, a03);
        a10 = fmaf(x1, w.x, a10); a11 = fmaf(x1, w.y, a11);
        a12 = fmaf(x1, w.z, a12); a13 = fmaf(x1, w.w, a13);
    }
    int row0 = rowbase + r0;
    if (row0 < N) {
        float4 o = make_float4(a00, a01, a02, a03);
        *(float4*)&g_h1[(size_t)row0 * 64 + cg * 4] = o;
    }
    if (row0 + 1 < N) {
        float4 o = make_float4(a10, a11, a12, a13);
        *(float4*)&g_h1[(size_t)(row0 + 1) * 64 + cg * 4] = o;
    }
}

// ---------------- attention dots layer 1 ----------------
__global__ void k_att1(const float* __restrict__ att_s,
                       const float* __restrict__ att_d, int N) {
    int t = blockIdx.x * blockDim.x + threadIdx.x;
    if (t >= N * 8) return;
    int n = t >> 3, h = t & 7;
    const float* hp = &g_h1[(size_t)n * 64 + h * 8];
    float s = 0.f, d = 0.f;
#pragma unroll
    for (int c = 0; c < 8; c++) {
        float v = hp[c];
        s = fmaf(v, att_s[h * 8 + c], s);
        d = fmaf(v, att_d[h * 8 + c], d);
    }
    g_as1[t] = s;
    g_ad1[t] = d;
}

// ---------------- aggregate layer 1 (warp per dst node) ----------------
__global__ void k_agg1(const float* __restrict__ b1, int N) {
    int warp = (blockIdx.x * blockDim.x + threadIdx.x) >> 5;
    int lane = threadIdx.x & 31;
    if (warp >= N) return;
    int n = warp;
    int c0 = lane * 2;
    int head = lane >> 2;
    float ad = g_ad1[n * 8 + head];
    int beg = g_off[n], end = g_off[n + 1];
    float acc0 = 0.f, acc1 = 0.f, den = 0.f;
    for (int e = beg; e < end; e++) {
        int src = g_csr[e];
        float as = __ldg(&g_as1[src * 8 + head]);
        float a = as + ad;
        a = (a > 0.f) ? a : 0.2f * a;
        float ex = __expf(a);
        den += ex;
        float2 hv = *(const float2*)&g_h1[(size_t)src * 64 + c0];
        acc0 = fmaf(ex, hv.x, acc0);
        acc1 = fmaf(ex, hv.y, acc1);
    }
    float inv = 1.f / (den + 1e-16f);
    float o0 = acc0 * inv + b1[c0];
    float o1 = acc1 * inv + b1[c0 + 1];
    o0 = (o0 > 0.f) ? o0 : (__expf(o0) - 1.f);  // elu
    o1 = (o1 > 0.f) ? o1 : (__expf(o1) - 1.f);
    g_hmid[(size_t)n * 64 + c0] = o0;
    g_hmid[(size_t)n * 64 + c0 + 1] = o1;
}

// ---------------- GEMM2 + attention dots layer 2 ----------------
// block 128 threads; 16-lane group per node (2 nodes per warp).
__global__ void k_gemm2(const float* __restrict__ W2,
                        const float* __restrict__ att_s,
                        const float* __restrict__ att_d, int N) {
    __shared__ float sW[64 * 16];
    __shared__ float sAs[16], sAd[16];
    int tid = threadIdx.x;
    for (int i = tid; i < 1024; i += 128) sW[i] = W2[i];
    if (tid < 16) {
        sAs[tid] = att_s[tid];
        sAd[tid] = att_d[tid];
    }
    __syncthreads();
    int gwarp = (blockIdx.x * 128 + tid) >> 5;
    int lane = tid & 31;
    int c = lane & 15;
    int sub = lane >> 4;
    int node = gwarp * 2 + sub;
    float acc = 0.f;
    if (node < N) {
        const float* hm = &g_hmid[(size_t)node * 64];
#pragma unroll 8
        for (int k = 0; k < 64; k++) acc = fmaf(__ldg(&hm[k]), sW[k * 16 + c], acc);
    }
    float p = acc * sAs[c], q = acc * sAd[c];
#pragma unroll
    for (int o = 8; o >= 1; o >>= 1) {
        p += __shfl_xor_sync(0xffffffffu, p, o);
        q += __shfl_xor_sync(0xffffffffu, q, o);
    }
    if (node < N) {
        g_h2[node * 16 + c] = acc;
        if (c == 0) {
            g_as2[node] = p;
            g_ad2[node] = q;
        }
    }
}

// ---------------- aggregate layer 2 + log_softmax (warp per dst) ----------
__global__ void k_agg2(const float* __restrict__ b2, float* __restrict__ out,
                       int N) {
    int warp = (blockIdx.x * blockDim.x + threadIdx.x) >> 5;
    if (warp >= N) return;
    int lane = threadIdx.x & 31;
    int c = lane & 15;
    int sub = lane >> 4;
    int n = warp;
    float ad = g_ad2[n];
    int beg = g_off[n], end = g_off[n + 1];
    float acc = 0.f, den = 0.f;
    for (int e = beg + sub; e < end; e += 2) {
        int src = g_csr[e];
        float as = __ldg(&g_as2[src]);
        float a = as + ad;
        a = (a > 0.f) ? a : 0.2f * a;
        float ex = __expf(a);
        den += ex;
        acc = fmaf(ex, __ldg(&g_h2[src * 16 + c]), acc);
    }
    acc += __shfl_xor_sync(0xffffffffu, acc, 16);
    den += __shfl_xor_sync(0xffffffffu, den, 16);
    float v = acc / (den + 1e-16f) + b2[c];
    float m = v;
#pragma unroll
    for (int o = 8; o >= 1; o >>= 1) m = fmaxf(m, __shfl_xor_sync(0xffffffffu, m, o));
    float s = __expf(v - m);
#pragma unroll
    for (int o = 8; o >= 1; o >>= 1) s += __shfl_xor_sync(0xffffffffu, s, o);
    float r = v - m - __logf(s);
    if (sub == 0) out[n * 16 + c] = r;
}

// ---------------------------------------------------------------------------
extern "C" void kernel_launch(void* const* d_in, const int* in_sizes, int n_in,
                              void* d_out, int out_size) {
    const float* x        = (const float*)d_in[0];
    const void*  ei       = d_in[1];
    const float* W1       = (const float*)d_in[2];
    const float* b1       = (const float*)d_in[3];
    const float* att_src1 = (const float*)d_in[4];
    const float* att_dst1 = (const float*)d_in[5];
    const float* W2       = (const float*)d_in[6];
    const float* b2       = (const float*)d_in[7];
    const float* att_src2 = (const float*)d_in[8];
    const float* att_dst2 = (const float*)d_in[9];
    float* out = (float*)d_out;

    int N = in_sizes[0] / 128;
    int E = in_sizes[1] / 2;
    if (N > N_MAX) N = N_MAX;
    if (E > E_MAX) E = E_MAX;

    int gE = (E + 255) / 256;
    int gN = (N + 255) / 256;
    int nblkScan = (N + SCAN_B - 1) / SCAN_B;

    k_detect<<<1, 256>>>((const unsigned int*)ei);
    k_decode<<<gE, 256>>>(ei, E);
    k_deginit<<<gN, 256>>>(N);
    k_degcount<<<gE, 256>>>(E);
    k_scan1<<<nblkScan, SCAN_B>>>(N);
    k_scan2<<<1, 32>>>(nblkScan, N);
    k_scan3<<<gN, 256>>>(N);
    k_scat_self<<<gN, 256>>>(N);
    k_scat_edge<<<gE, 256>>>(E);

    k_gemm1<<<(N + 31) / 32, 256>>>(x, W1, N);
    k_att1<<<(N * 8 + 255) / 256, 256>>>(att_src1, att_dst1, N);
    k_agg1<<<(N + 7) / 8, 256>>>(b1, N);

    k_gemm2<<<(N + 7) / 8, 128>>>(W2, att_src2, att_dst2, N);
    k_agg2<<<(N + 7) / 8, 256>>>(b2, out, N);
}

// round 4
// speedup vs baseline: 1.4573x; 1.4573x over previous
#include <cuda_runtime.h>
#include <cuda_bf16.h>
#include <cstdint>

#define N_MAX 100000
#define E_MAX 1600000
#define T_MAX (E_MAX + N_MAX)
#define SCAN_B 1024
#define NBLK_SCAN_MAX 128

// scratch (device globals: allocation-free)
__device__ float g_h1[N_MAX * 64];
__device__ float g_as1[N_MAX * 8];
__device__ float g_ad1[N_MAX * 8];
__device__ float g_hmid[N_MAX * 64];
__device__ float g_h2[N_MAX * 16];
__device__ float g_as2[N_MAX];
__device__ float g_ad2[N_MAX];
__device__ int   g_src[E_MAX];
__device__ int   g_dst[E_MAX];
__device__ int   g_deg[N_MAX];
__device__ int   g_off[N_MAX + 1];
__device__ int   g_cur[N_MAX];
__device__ int   g_csr[T_MAX];
__device__ int   g_bsum[NBLK_SCAN_MAX];
__device__ int   g_is64;

// ---------------- f32x2 packed helpers ----------------
__device__ __forceinline__ unsigned long long pk2(float a, float b) {
    unsigned long long r;
    asm("mov.b64 %0, {%1, %2};" : "=l"(r) : "f"(a), "f"(b));
    return r;
}
__device__ __forceinline__ void fma2(unsigned long long& d, unsigned long long a,
                                     unsigned long long b) {
    asm("fma.rn.f32x2 %0, %1, %2, %0;" : "+l"(d) : "l"(a), "l"(b));
}
__device__ __forceinline__ float2 up2(unsigned long long v) {
    float2 r;
    asm("mov.b64 {%0, %1}, %2;" : "=f"(r.x), "=f"(r.y) : "l"(v));
    return r;
}

// ---------------- edge dtype detect ----------------
__global__ void k_detect(const unsigned int* __restrict__ w) {
    __shared__ int cnt;
    if (threadIdx.x == 0) cnt = 0;
    __syncthreads();
    int z = 0;
    for (int i = threadIdx.x; i < 2048; i += blockDim.x)
        if (w[2 * i + 1] == 0u) z++;
    atomicAdd(&cnt, z);
    __syncthreads();
    if (threadIdx.x == 0) g_is64 = (cnt > 1024) ? 1 : 0;
}

__global__ void k_deginit(int N) {
    int i = blockIdx.x * blockDim.x + threadIdx.x;
    if (i < N) g_deg[i] = 1;  // self loop
}

// decode + degree count fused
__global__ void k_decode_deg(const void* __restrict__ ei, int E) {
    int e = blockIdx.x * blockDim.x + threadIdx.x;
    if (e >= E) return;
    int s, d;
    if (g_is64) {
        const long long* p = (const long long*)ei;
        s = (int)p[e];
        d = (int)p[e + E];
    } else {
        const int* p = (const int*)ei;
        s = p[e];
        d = p[e + E];
    }
    g_src[e] = s;
    g_dst[e] = d;
    atomicAdd(&g_deg[d], 1);
}

// ---------------- scan ----------------
__global__ void k_scan1(int N) {
    __shared__ int s[SCAN_B];
    int i = blockIdx.x * SCAN_B + threadIdx.x;
    int v = (i < N) ? g_deg[i] : 0;
    s[threadIdx.x] = v;
    __syncthreads();
    for (int off = 1; off < SCAN_B; off <<= 1) {
        int t = 0;
        if ((int)threadIdx.x >= off) t = s[threadIdx.x - off];
        __syncthreads();
        s[threadIdx.x] += t;
        __syncthreads();
    }
    if (i < N) g_off[i] = s[threadIdx.x] - v;
    if (threadIdx.x == SCAN_B - 1) g_bsum[blockIdx.x] = s[threadIdx.x];
}
__global__ void k_scan2(int nblk, int N) {
    if (threadIdx.x == 0) {
        int run = 0;
        for (int b = 0; b < nblk; b++) {
            int t = g_bsum[b];
            g_bsum[b] = run;
            run += t;
        }
        g_off[N] = run;
    }
}
// finalize offsets + self-loop scatter fused
__global__ void k_scan3(int N) {
    int i = blockIdx.x * blockDim.x + threadIdx.x;
    if (i < N) {
        int o = g_off[i] + g_bsum[i / SCAN_B];
        g_off[i] = o;
        g_csr[o] = i;       // self loop first
        g_cur[i] = o + 1;
    }
}
__global__ void k_scat_edge(int E) {
    int e = blockIdx.x * blockDim.x + threadIdx.x;
    if (e < E) g_csr[atomicAdd(&g_cur[g_dst[e]], 1)] = g_src[e];
}

// ---------------- GEMM1: h1 = x @ W1 ([N,128]x[128,64]) -------------------
// 128 threads/block, block tile 128 rows x 64 cols, f32x2 packed FMA.
// dyn smem: sW 32KB + sX 64KB (swizzled) = 96KB.
#define SXI(r, kq) ((r) * 128 + ((((kq) ^ ((r) & 7))) << 2))

__global__ void __launch_bounds__(128) k_gemm1(const float* __restrict__ x,
                                               const float* __restrict__ W, int N) {
    extern __shared__ float smem[];
    float* sW = smem;          // 128*64
    float* sX = smem + 8192;   // 128*128 swizzled
    int tid = threadIdx.x;

    const float4* W4 = (const float4*)W;
    float4* sW4 = (float4*)sW;
#pragma unroll
    for (int i = tid; i < 2048; i += 128) sW4[i] = W4[i];

    int rowbase = blockIdx.x * 128;
    const float4* x4 = (const float4*)x;
#pragma unroll
    for (int idx = tid; idx < 4096; idx += 128) {
        int r = idx >> 5, kq = idx & 31;
        int row = rowbase + r;
        float4 v = make_float4(0.f, 0.f, 0.f, 0.f);
        if (row < N) v = x4[(size_t)row * 32 + kq];
        *(float4*)&sX[SXI(r, kq)] = v;
    }
    __syncthreads();

    int rowthr = tid >> 3;  // 0..15 ; rows rowthr+16*i
    int colthr = tid & 7;   // 0..7  ; cols c0..c0+3, c0+32..c0+35
    int c0 = colthr * 4;

    unsigned long long acc[8][4];
#pragma unroll
    for (int i = 0; i < 8; i++)
#pragma unroll
        for (int j = 0; j < 4; j++) acc[i][j] = 0ULL;

#pragma unroll 4
    for (int kq = 0; kq < 32; kq++) {
        float4 xq[8];
#pragma unroll
        for (int i = 0; i < 8; i++) xq[i] = *(const float4*)&sX[SXI(rowthr + 16 * i, kq)];
#pragma unroll
        for (int kk = 0; kk < 4; kk++) {
            int k = kq * 4 + kk;
            float4 wa = *(const float4*)&sW[k * 64 + c0];
            float4 wb = *(const float4*)&sW[k * 64 + c0 + 32];
            unsigned long long w0 = pk2(wa.x, wa.y), w1 = pk2(wa.z, wa.w);
            unsigned long long w2 = pk2(wb.x, wb.y), w3 = pk2(wb.z, wb.w);
#pragma unroll
            for (int i = 0; i < 8; i++) {
                float xv = ((const float*)&xq[i])[kk];
                unsigned long long xd = pk2(xv, xv);
                fma2(acc[i][0], xd, w0);
                fma2(acc[i][1], xd, w1);
                fma2(acc[i][2], xd, w2);
                fma2(acc[i][3], xd, w3);
            }
        }
    }

#pragma unroll
    for (int i = 0; i < 8; i++) {
        int row = rowbase + rowthr + 16 * i;
        if (row >= N) continue;
        float2 p0 = up2(acc[i][0]), p1 = up2(acc[i][1]);
        float2 p2 = up2(acc[i][2]), p3 = up2(acc[i][3]);
        *(float4*)&g_h1[(size_t)row * 64 + c0] = make_float4(p0.x, p0.y, p1.x, p1.y);
        *(float4*)&g_h1[(size_t)row * 64 + c0 + 32] = make_float4(p2.x, p2.y, p3.x, p3.y);
    }
}

// ---------------- attention dots layer 1 ----------------
__global__ void k_att1(const float* __restrict__ att_s,
                       const float* __restrict__ att_d, int N) {
    int t = blockIdx.x * blockDim.x + threadIdx.x;
    if (t >= N * 8) return;
    int n = t >> 3, h = t & 7;
    const float* hp = &g_h1[(size_t)n * 64 + h * 8];
    float s = 0.f, d = 0.f;
#pragma unroll
    for (int c = 0; c < 8; c++) {
        float v = hp[c];
        s = fmaf(v, att_s[h * 8 + c], s);
        d = fmaf(v, att_d[h * 8 + c], d);
    }
    g_as1[t] = s;
    g_ad1[t] = d;
}

// ---------------- aggregate layer 1: warp/node, 2 edges x 16 lanes --------
__global__ void k_agg1(const float* __restrict__ b1, int N) {
    int warp = (blockIdx.x * blockDim.x + threadIdx.x) >> 5;
    if (warp >= N) return;
    int lane = threadIdx.x & 31;
    int sub = lane >> 4;       // 0/1 edge slot
    int q = lane & 15;         // channel quad
    int c0 = q * 4;
    int head = q >> 1;
    int n = warp;
    float ad = g_ad1[n * 8 + head];
    int beg = g_off[n], end = g_off[n + 1];
    float a0 = 0.f, a1 = 0.f, a2 = 0.f, a3 = 0.f, den = 0.f;
    for (int e = beg + sub; e < end; e += 2) {
        int src = __ldg(&g_csr[e]);
        float as = __ldg(&g_as1[src * 8 + head]);
        float a = as + ad;
        a = (a > 0.f) ? a : 0.2f * a;
        float ex = __expf(a);
        den += ex;
        float4 hv = *(const float4*)&g_h1[(size_t)src * 64 + c0];
        a0 = fmaf(ex, hv.x, a0);
        a1 = fmaf(ex, hv.y, a1);
        a2 = fmaf(ex, hv.z, a2);
        a3 = fmaf(ex, hv.w, a3);
    }
    a0 += __shfl_xor_sync(0xffffffffu, a0, 16);
    a1 += __shfl_xor_sync(0xffffffffu, a1, 16);
    a2 += __shfl_xor_sync(0xffffffffu, a2, 16);
    a3 += __shfl_xor_sync(0xffffffffu, a3, 16);
    den += __shfl_xor_sync(0xffffffffu, den, 16);
    if (sub == 0) {
        float inv = 1.f / (den + 1e-16f);
        float o0 = a0 * inv + b1[c0];
        float o1 = a1 * inv + b1[c0 + 1];
        float o2 = a2 * inv + b1[c0 + 2];
        float o3 = a3 * inv + b1[c0 + 3];
        o0 = (o0 > 0.f) ? o0 : (__expf(o0) - 1.f);
        o1 = (o1 > 0.f) ? o1 : (__expf(o1) - 1.f);
        o2 = (o2 > 0.f) ? o2 : (__expf(o2) - 1.f);
        o3 = (o3 > 0.f) ? o3 : (__expf(o3) - 1.f);
        *(float4*)&g_hmid[(size_t)n * 64 + c0] = make_float4(o0, o1, o2, o3);
    }
}

// ---------------- GEMM2 + att dots layer 2 (smem staged) ------------------
// 256 threads, 16 nodes/block; thread = (node_local = tid>>4, c = tid&15)
__global__ void k_gemm2(const float* __restrict__ W2,
                        const float* __restrict__ att_s,
                        const float* __restrict__ att_d, int N) {
    __shared__ float sW[64 * 16];
    __shared__ float sH[16 * 64];
    __shared__ float sAs[16], sAd[16];
    int tid = threadIdx.x;
    ((float4*)sW)[tid] = ((const float4*)W2)[tid];
    if (tid < 16) {
        sAs[tid] = att_s[tid];
        sAd[tid] = att_d[tid];
    }
    int base = blockIdx.x * 16;
    {
        int r = tid >> 4, kq = tid & 15;
        int node = base + r;
        float4 v = make_float4(0.f, 0.f, 0.f, 0.f);
        if (node < N) v = *(const float4*)&g_hmid[(size_t)node * 64 + kq * 4];
        *(float4*)&sH[r * 64 + kq * 4] = v;
    }
    __syncthreads();

    int nl = tid >> 4, c = tid & 15;
    int node = base + nl;
    float acc = 0.f;
#pragma unroll
    for (int kq = 0; kq < 16; kq++) {
        float4 h = *(const float4*)&sH[nl * 64 + kq * 4];
        acc = fmaf(h.x, sW[(kq * 4 + 0) * 16 + c], acc);
        acc = fmaf(h.y, sW[(kq * 4 + 1) * 16 + c], acc);
        acc = fmaf(h.z, sW[(kq * 4 + 2) * 16 + c], acc);
        acc = fmaf(h.w, sW[(kq * 4 + 3) * 16 + c], acc);
    }
    float p = acc * sAs[c], q = acc * sAd[c];
#pragma unroll
    for (int o = 8; o >= 1; o >>= 1) {
        p += __shfl_xor_sync(0xffffffffu, p, o);
        q += __shfl_xor_sync(0xffffffffu, q, o);
    }
    if (node < N) {
        g_h2[node * 16 + c] = acc;
        if (c == 0) {
            g_as2[node] = p;
            g_ad2[node] = q;
        }
    }
}

// ---------------- aggregate layer 2 + log_softmax: 4 edges x 8 lanes ------
__global__ void k_agg2(const float* __restrict__ b2, float* __restrict__ out,
                       int N) {
    int warp = (blockIdx.x * blockDim.x + threadIdx.x) >> 5;
    if (warp >= N) return;
    int lane = threadIdx.x & 31;
    int sub = lane >> 3;  // 0..3 edge slot
    int cg = lane & 7;
    int c0 = cg * 2;
    int n = warp;
    float ad = g_ad2[n];
    int beg = g_off[n], end = g_off[n + 1];
    float ax = 0.f, ay = 0.f, den = 0.f;
    for (int e = beg + sub; e < end; e += 4) {
        int src = __ldg(&g_csr[e]);
        float as = __ldg(&g_as2[src]);
        float a = as + ad;
        a = (a > 0.f) ? a : 0.2f * a;
        float ex = __expf(a);
        den += ex;
        float2 hv = *(const float2*)&g_h2[src * 16 + c0];
        ax = fmaf(ex, hv.x, ax);
        ay = fmaf(ex, hv.y, ay);
    }
    ax += __shfl_xor_sync(0xffffffffu, ax, 8);
    ax += __shfl_xor_sync(0xffffffffu, ax, 16);
    ay += __shfl_xor_sync(0xffffffffu, ay, 8);
    ay += __shfl_xor_sync(0xffffffffu, ay, 16);
    den += __shfl_xor_sync(0xffffffffu, den, 8);
    den += __shfl_xor_sync(0xffffffffu, den, 16);
    float inv = 1.f / (den + 1e-16f);
    float v0 = ax * inv + b2[c0];
    float v1 = ay * inv + b2[c0 + 1];
    float m = fmaxf(v0, v1);
#pragma unroll
    for (int o = 4; o >= 1; o >>= 1) m = fmaxf(m, __shfl_xor_sync(0xffffffffu, m, o));
    float s = __expf(v0 - m) + __expf(v1 - m);
#pragma unroll
    for (int o = 4; o >= 1; o >>= 1) s += __shfl_xor_sync(0xffffffffu, s, o);
    float ls = __logf(s);
    if (sub == 0) {
        out[n * 16 + c0] = v0 - m - ls;
        out[n * 16 + c0 + 1] = v1 - m - ls;
    }
}

// ---------------------------------------------------------------------------
extern "C" void kernel_launch(void* const* d_in, const int* in_sizes, int n_in,
                              void* d_out, int out_size) {
    const float* x        = (const float*)d_in[0];
    const void*  ei       = d_in[1];
    const float* W1       = (const float*)d_in[2];
    const float* b1       = (const float*)d_in[3];
    const float* att_src1 = (const float*)d_in[4];
    const float* att_dst1 = (const float*)d_in[5];
    const float* W2       = (const float*)d_in[6];
    const float* b2       = (const float*)d_in[7];
    const float* att_src2 = (const float*)d_in[8];
    const float* att_dst2 = (const float*)d_in[9];
    float* out = (float*)d_out;

    int N = in_sizes[0] / 128;
    int E = in_sizes[1] / 2;
    if (N > N_MAX) N = N_MAX;
    if (E > E_MAX) E = E_MAX;

    int gE = (E + 255) / 256;
    int gN = (N + 255) / 256;
    int nblkScan = (N + SCAN_B - 1) / SCAN_B;

    k_detect<<<1, 256>>>((const unsigned int*)ei);
    k_deginit<<<gN, 256>>>(N);
    k_decode_deg<<<gE, 256>>>(ei, E);
    k_scan1<<<nblkScan, SCAN_B>>>(N);
    k_scan2<<<1, 32>>>(nblkScan, N);
    k_scan3<<<gN, 256>>>(N);
    k_scat_edge<<<gE, 256>>>(E);

    (void)cudaFuncSetAttribute(k_gemm1,
                               cudaFuncAttributeMaxDynamicSharedMemorySize, 98304);
    k_gemm1<<<(N + 127) / 128, 128, 98304>>>(x, W1, N);
    k_att1<<<(N * 8 + 255) / 256, 256>>>(att_src1, att_dst1, N);
    k_agg1<<<(N * 32 + 255) / 256, 256>>>(b1, N);

    k_gemm2<<<(N + 15) / 16, 256>>>(W2, att_src2, att_dst2, N);
    k_agg2<<<(N * 32 + 255) / 256, 256>>>(b2, out, N);
}

// round 5
// speedup vs baseline: 1.5025x; 1.0310x over previous
#include <cuda_runtime.h>
#include <cuda_fp16.h>
#include <cuda_bf16.h>
#include <cstdint>

#define N_MAX 100000
#define E_MAX 1600000
#define T_MAX (E_MAX + N_MAX)
#define SCAN_B 1024
#define NBLK_SCAN_MAX 128

// scratch (device globals: allocation-free)
__device__ float  g_h1[N_MAX * 64];
__device__ __half g_h1h[N_MAX * 64];
__device__ float  g_as1[N_MAX * 8];
__device__ float  g_ad1[N_MAX * 8];
__device__ float  g_hmid[N_MAX * 64];
__device__ float  g_h2[N_MAX * 16];
__device__ float  g_as2[N_MAX];
__device__ float  g_ad2[N_MAX];
__device__ int    g_src[E_MAX];
__device__ int    g_dst[E_MAX];
__device__ int    g_rank[E_MAX];
__device__ int    g_deg[N_MAX];
__device__ int    g_off[N_MAX + 1];
__device__ int    g_csr[T_MAX];
__device__ int    g_bsum[NBLK_SCAN_MAX];
__device__ int    g_is64;

// ---------------- f32x2 packed helpers ----------------
__device__ __forceinline__ unsigned long long pk2(float a, float b) {
    unsigned long long r;
    asm("mov.b64 %0, {%1, %2};" : "=l"(r) : "f"(a), "f"(b));
    return r;
}
__device__ __forceinline__ void fma2(unsigned long long& d, unsigned long long a,
                                     unsigned long long b) {
    asm("fma.rn.f32x2 %0, %1, %2, %0;" : "+l"(d) : "l"(a), "l"(b));
}
__device__ __forceinline__ float2 up2(unsigned long long v) {
    float2 r;
    asm("mov.b64 {%0, %1}, %2;" : "=f"(r.x), "=f"(r.y) : "l"(v));
    return r;
}

// ---------------- init: deg=1 everywhere + dtype detect (block 0) ---------
__global__ void k_init(const unsigned int* __restrict__ w, int N) {
    int i = blockIdx.x * blockDim.x + threadIdx.x;
    if (i < N) g_deg[i] = 1;  // self loop
    if (blockIdx.x == 0) {
        __shared__ int cnt;
        if (threadIdx.x == 0) cnt = 0;
        __syncthreads();
        int z = 0;
        for (int j = threadIdx.x; j < 2048; j += blockDim.x)
            if (w[2 * j + 1] == 0u) z++;
        atomicAdd(&cnt, z);
        __syncthreads();
        if (threadIdx.x == 0) g_is64 = (cnt > 1024) ? 1 : 0;
    }
}

// decode + degree count; atomic return value = slot rank (atomic-free scatter)
__global__ void k_decode_deg(const void* __restrict__ ei, int E) {
    int e = blockIdx.x * blockDim.x + threadIdx.x;
    if (e >= E) return;
    int s, d;
    if (g_is64) {
        const long long* p = (const long long*)ei;
        s = (int)p[e];
        d = (int)p[e + E];
    } else {
        const int* p = (const int*)ei;
        s = p[e];
        d = p[e + E];
    }
    g_src[e] = s;
    g_dst[e] = d;
    g_rank[e] = atomicAdd(&g_deg[d], 1);  // >=1 (self loop occupies slot 0)
}

// ---------------- scan (warp-shuffle based) ----------------
__global__ void k_scan1(int N) {
    __shared__ int wsum[32];
    int i = blockIdx.x * SCAN_B + threadIdx.x;
    int v = (i < N) ? g_deg[i] : 0;
    int lane = threadIdx.x & 31, wid = threadIdx.x >> 5;
    int s = v;
#pragma unroll
    for (int o = 1; o < 32; o <<= 1) {
        int t = __shfl_up_sync(0xffffffffu, s, o);
        if (lane >= o) s += t;
    }
    if (lane == 31) wsum[wid] = s;
    __syncthreads();
    if (wid == 0) {
        int ws = wsum[lane];
#pragma unroll
        for (int o = 1; o < 32; o <<= 1) {
            int t = __shfl_up_sync(0xffffffffu, ws, o);
            if (lane >= o) ws += t;
        }
        wsum[lane] = ws;
    }
    __syncthreads();
    int base = (wid > 0) ? wsum[wid - 1] : 0;
    if (i < N) g_off[i] = base + s - v;  // block-local exclusive
    if (threadIdx.x == 0) g_bsum[blockIdx.x] = wsum[31];
}
__global__ void k_scan2(int nblk, int N) {
    if (threadIdx.x == 0) {
        int run = 0;
        for (int b = 0; b < nblk; b++) {
            int t = g_bsum[b];
            g_bsum[b] = run;
            run += t;
        }
        g_off[N] = run;
    }
}
// finalize offsets + self-loop scatter fused
__global__ void k_scan3(int N) {
    int i = blockIdx.x * blockDim.x + threadIdx.x;
    if (i < N) {
        int o = g_off[i] + g_bsum[i / SCAN_B];
        g_off[i] = o;
        g_csr[o] = i;  // self loop slot 0
    }
}
// atomic-free scatter using precomputed ranks
__global__ void k_scat_edge(int E) {
    int e = blockIdx.x * blockDim.x + threadIdx.x;
    if (e < E) g_csr[__ldg(&g_off[g_dst[e]]) + g_rank[e]] = g_src[e];
}

// ---------------- GEMM1: h1 = x @ W1 ([N,128]x[128,64]) -------------------
#define SXI(r, kq) ((r) * 128 + ((((kq) ^ ((r) & 7))) << 2))

__global__ void __launch_bounds__(128) k_gemm1(const float* __restrict__ x,
                                               const float* __restrict__ W, int N) {
    extern __shared__ float smem[];
    float* sW = smem;          // 128*64
    float* sX = smem + 8192;   // 128*128 swizzled
    int tid = threadIdx.x;

    const float4* W4 = (const float4*)W;
    float4* sW4 = (float4*)sW;
#pragma unroll
    for (int i = tid; i < 2048; i += 128) sW4[i] = W4[i];

    int rowbase = blockIdx.x * 128;
    const float4* x4 = (const float4*)x;
#pragma unroll
    for (int idx = tid; idx < 4096; idx += 128) {
        int r = idx >> 5, kq = idx & 31;
        int row = rowbase + r;
        float4 v = make_float4(0.f, 0.f, 0.f, 0.f);
        if (row < N) v = x4[(size_t)row * 32 + kq];
        *(float4*)&sX[SXI(r, kq)] = v;
    }
    __syncthreads();

    int rowthr = tid >> 3;  // 0..15 ; rows rowthr+16*i
    int colthr = tid & 7;   // 0..7
    int c0 = colthr * 4;

    unsigned long long acc[8][4];
#pragma unroll
    for (int i = 0; i < 8; i++)
#pragma unroll
        for (int j = 0; j < 4; j++) acc[i][j] = 0ULL;

#pragma unroll 4
    for (int kq = 0; kq < 32; kq++) {
        float4 xq[8];
#pragma unroll
        for (int i = 0; i < 8; i++) xq[i] = *(const float4*)&sX[SXI(rowthr + 16 * i, kq)];
#pragma unroll
        for (int kk = 0; kk < 4; kk++) {
            int k = kq * 4 + kk;
            float4 wa = *(const float4*)&sW[k * 64 + c0];
            float4 wb = *(const float4*)&sW[k * 64 + c0 + 32];
            unsigned long long w0 = pk2(wa.x, wa.y), w1 = pk2(wa.z, wa.w);
            unsigned long long w2 = pk2(wb.x, wb.y), w3 = pk2(wb.z, wb.w);
#pragma unroll
            for (int i = 0; i < 8; i++) {
                float xv = ((const float*)&xq[i])[kk];
                unsigned long long xd = pk2(xv, xv);
                fma2(acc[i][0], xd, w0);
                fma2(acc[i][1], xd, w1);
                fma2(acc[i][2], xd, w2);
                fma2(acc[i][3], xd, w3);
            }
        }
    }

#pragma unroll
    for (int i = 0; i < 8; i++) {
        int row = rowbase + rowthr + 16 * i;
        if (row >= N) continue;
        float2 p0 = up2(acc[i][0]), p1 = up2(acc[i][1]);
        float2 p2 = up2(acc[i][2]), p3 = up2(acc[i][3]);
        *(float4*)&g_h1[(size_t)row * 64 + c0] = make_float4(p0.x, p0.y, p1.x, p1.y);
        *(float4*)&g_h1[(size_t)row * 64 + c0 + 32] = make_float4(p2.x, p2.y, p3.x, p3.y);
        // fp16 copy for the edge-gather path
        __half2 h0 = __floats2half2_rn(p0.x, p0.y);
        __half2 h1v = __floats2half2_rn(p1.x, p1.y);
        __half2 h2v = __floats2half2_rn(p2.x, p2.y);
        __half2 h3 = __floats2half2_rn(p3.x, p3.y);
        uint2 u0, u1;
        u0.x = *(unsigned*)&h0;  u0.y = *(unsigned*)&h1v;
        u1.x = *(unsigned*)&h2v; u1.y = *(unsigned*)&h3;
        *(uint2*)&g_h1h[(size_t)row * 64 + c0] = u0;
        *(uint2*)&g_h1h[(size_t)row * 64 + c0 + 32] = u1;
    }
}

// ---------------- attention dots layer 1 ----------------
__global__ void k_att1(const float* __restrict__ att_s,
                       const float* __restrict__ att_d, int N) {
    int t = blockIdx.x * blockDim.x + threadIdx.x;
    if (t >= N * 8) return;
    int n = t >> 3, h = t & 7;
    const float* hp = &g_h1[(size_t)n * 64 + h * 8];
    float s = 0.f, d = 0.f;
#pragma unroll
    for (int c = 0; c < 8; c++) {
        float v = hp[c];
        s = fmaf(v, att_s[h * 8 + c], s);
        d = fmaf(v, att_d[h * 8 + c], d);
    }
    g_as1[t] = s;
    g_ad1[t] = d;
}

// ---------------- aggregate layer 1: warp/node, 2 edges x 16 lanes, fp16 --
__global__ void k_agg1(const float* __restrict__ b1, int N) {
    int warp = (blockIdx.x * blockDim.x + threadIdx.x) >> 5;
    if (warp >= N) return;
    int lane = threadIdx.x & 31;
    int sub = lane >> 4;       // 0/1 edge slot
    int q = lane & 15;         // channel quad
    int c0 = q * 4;
    int head = q >> 1;
    int n = warp;
    float ad = g_ad1[n * 8 + head];
    int beg = g_off[n], end = g_off[n + 1];
    float a0 = 0.f, a1 = 0.f, a2 = 0.f, a3 = 0.f, den = 0.f;
    for (int e = beg + sub; e < end; e += 2) {
        int src = __ldg(&g_csr[e]);
        float as = __ldg(&g_as1[src * 8 + head]);
        float a = as + ad;
        a = (a > 0.f) ? a : 0.2f * a;
        float ex = __expf(a);
        den += ex;
        uint2 hv = *(const uint2*)&g_h1h[(size_t)src * 64 + c0];
        float2 p0 = __half22float2(*(__half2*)&hv.x);
        float2 p1 = __half22float2(*(__half2*)&hv.y);
        a0 = fmaf(ex, p0.x, a0);
        a1 = fmaf(ex, p0.y, a1);
        a2 = fmaf(ex, p1.x, a2);
        a3 = fmaf(ex, p1.y, a3);
    }
    a0 += __shfl_xor_sync(0xffffffffu, a0, 16);
    a1 += __shfl_xor_sync(0xffffffffu, a1, 16);
    a2 += __shfl_xor_sync(0xffffffffu, a2, 16);
    a3 += __shfl_xor_sync(0xffffffffu, a3, 16);
    den += __shfl_xor_sync(0xffffffffu, den, 16);
    if (sub == 0) {
        float inv = 1.f / (den + 1e-16f);
        float o0 = a0 * inv + b1[c0];
        float o1 = a1 * inv + b1[c0 + 1];
        float o2 = a2 * inv + b1[c0 + 2];
        float o3 = a3 * inv + b1[c0 + 3];
        o0 = (o0 > 0.f) ? o0 : (__expf(o0) - 1.f);
        o1 = (o1 > 0.f) ? o1 : (__expf(o1) - 1.f);
        o2 = (o2 > 0.f) ? o2 : (__expf(o2) - 1.f);
        o3 = (o3 > 0.f) ? o3 : (__expf(o3) - 1.f);
        *(float4*)&g_hmid[(size_t)n * 64 + c0] = make_float4(o0, o1, o2, o3);
    }
}

// ---------------- GEMM2 + att dots layer 2 (smem staged) ------------------
__global__ void k_gemm2(const float* __restrict__ W2,
                        const float* __restrict__ att_s,
                        const float* __restrict__ att_d, int N) {
    __shared__ float sW[64 * 16];
    __shared__ float sH[16 * 64];
    __shared__ float sAs[16], sAd[16];
    int tid = threadIdx.x;
    ((float4*)sW)[tid] = ((const float4*)W2)[tid];
    if (tid < 16) {
        sAs[tid] = att_s[tid];
        sAd[tid] = att_d[tid];
    }
    int base = blockIdx.x * 16;
    {
        int r = tid >> 4, kq = tid & 15;
        int node = base + r;
        float4 v = make_float4(0.f, 0.f, 0.f, 0.f);
        if (node < N) v = *(const float4*)&g_hmid[(size_t)node * 64 + kq * 4];
        *(float4*)&sH[r * 64 + kq * 4] = v;
    }
    __syncthreads();

    int nl = tid >> 4, c = tid & 15;
    int node = base + nl;
    float acc = 0.f;
#pragma unroll
    for (int kq = 0; kq < 16; kq++) {
        float4 h = *(const float4*)&sH[nl * 64 + kq * 4];
        acc = fmaf(h.x, sW[(kq * 4 + 0) * 16 + c], acc);
        acc = fmaf(h.y, sW[(kq * 4 + 1) * 16 + c], acc);
        acc = fmaf(h.z, sW[(kq * 4 + 2) * 16 + c], acc);
        acc = fmaf(h.w, sW[(kq * 4 + 3) * 16 + c], acc);
    }
    float p = acc * sAs[c], q = acc * sAd[c];
#pragma unroll
    for (int o = 8; o >= 1; o >>= 1) {
        p += __shfl_xor_sync(0xffffffffu, p, o);
        q += __shfl_xor_sync(0xffffffffu, q, o);
    }
    if (node < N) {
        g_h2[node * 16 + c] = acc;
        if (c == 0) {
            g_as2[node] = p;
            g_ad2[node] = q;
        }
    }
}

// ---------------- aggregate layer 2 + log_softmax: 4 edges x 8 lanes ------
__global__ void k_agg2(const float* __restrict__ b2, float* __restrict__ out,
                       int N) {
    int warp = (blockIdx.x * blockDim.x + threadIdx.x) >> 5;
    if (warp >= N) return;
    int lane = threadIdx.x & 31;
    int sub = lane >> 3;  // 0..3 edge slot
    int cg = lane & 7;
    int c0 = cg * 2;
    int n = warp;
    float ad = g_ad2[n];
    int beg = g_off[n], end = g_off[n + 1];
    float ax = 0.f, ay = 0.f, den = 0.f;
    for (int e = beg + sub; e < end; e += 4) {
        int src = __ldg(&g_csr[e]);
        float as = __ldg(&g_as2[src]);
        float a = as + ad;
        a = (a > 0.f) ? a : 0.2f * a;
        float ex = __expf(a);
        den += ex;
        float2 hv = *(const float2*)&g_h2[src * 16 + c0];
        ax = fmaf(ex, hv.x, ax);
        ay = fmaf(ex, hv.y, ay);
    }
    ax += __shfl_xor_sync(0xffffffffu, ax, 8);
    ax += __shfl_xor_sync(0xffffffffu, ax, 16);
    ay += __shfl_xor_sync(0xffffffffu, ay, 8);
    ay += __shfl_xor_sync(0xffffffffu, ay, 16);
    den += __shfl_xor_sync(0xffffffffu, den, 8);
    den += __shfl_xor_sync(0xffffffffu, den, 16);
    float inv = 1.f / (den + 1e-16f);
    float v0 = ax * inv + b2[c0];
    float v1 = ay * inv + b2[c0 + 1];
    float m = fmaxf(v0, v1);
#pragma unroll
    for (int o = 4; o >= 1; o >>= 1) m = fmaxf(m, __shfl_xor_sync(0xffffffffu, m, o));
    float s = __expf(v0 - m) + __expf(v1 - m);
#pragma unroll
    for (int o = 4; o >= 1; o >>= 1) s += __shfl_xor_sync(0xffffffffu, s, o);
    float ls = __logf(s);
    if (sub == 0) {
        out[n * 16 + c0] = v0 - m - ls;
        out[n * 16 + c0 + 1] = v1 - m - ls;
    }
}

// ---------------------------------------------------------------------------
extern "C" void kernel_launch(void* const* d_in, const int* in_sizes, int n_in,
                              void* d_out, int out_size) {
    const float* x        = (const float*)d_in[0];
    const void*  ei       = d_in[1];
    const float* W1       = (const float*)d_in[2];
    const float* b1       = (const float*)d_in[3];
    const float* att_src1 = (const float*)d_in[4];
    const float* att_dst1 = (const float*)d_in[5];
    const float* W2       = (const float*)d_in[6];
    const float* b2       = (const float*)d_in[7];
    const float* att_src2 = (const float*)d_in[8];
    const float* att_dst2 = (const float*)d_in[9];
    float* out = (float*)d_out;

    int N = in_sizes[0] / 128;
    int E = in_sizes[1] / 2;
    if (N > N_MAX) N = N_MAX;
    if (E > E_MAX) E = E_MAX;

    int gE = (E + 255) / 256;
    int gN = (N + 255) / 256;
    int nblkScan = (N + SCAN_B - 1) / SCAN_B;

    k_init<<<gN, 256>>>((const unsigned int*)ei, N);
    k_decode_deg<<<gE, 256>>>(ei, E);
    k_scan1<<<nblkScan, SCAN_B>>>(N);
    k_scan2<<<1, 32>>>(nblkScan, N);
    k_scan3<<<gN, 256>>>(N);
    k_scat_edge<<<gE, 256>>>(E);

    (void)cudaFuncSetAttribute(k_gemm1,
                               cudaFuncAttributeMaxDynamicSharedMemorySize, 98304);
    k_gemm1<<<(N + 127) / 128, 128, 98304>>>(x, W1, N);
    k_att1<<<(N * 8 + 255) / 256, 256>>>(att_src1, att_dst1, N);
    k_agg1<<<(N * 32 + 255) / 256, 256>>>(b1, N);

    k_gemm2<<<(N + 15) / 16, 256>>>(W2, att_src2, att_dst2, N);
    k_agg2<<<(N * 32 + 255) / 256, 256>>>(b2, out, N);
}

// round 6
// speedup vs baseline: 1.6367x; 1.0893x over previous
#include <cuda_runtime.h>
#include <cuda_fp16.h>
#include <cuda_bf16.h>
#include <cstdint>

#define N_MAX 100000
#define E_MAX 1600000
#define T_MAX (E_MAX + N_MAX)
#define SCAN_B 1024
#define NBLK_SCAN_MAX 128

// scratch (device globals: allocation-free)
__device__ __half g_h1h[N_MAX * 64];
__device__ float  g_as1[N_MAX * 8];
__device__ float  g_ad1[N_MAX * 8];
__device__ float  g_hmid[N_MAX * 64];
__device__ float  g_h2[N_MAX * 16];
__device__ float  g_as2[N_MAX];
__device__ float  g_ad2[N_MAX];
__device__ int    g_src[E_MAX];
__device__ unsigned long long g_dr[E_MAX];  // rank<<32 | dst
__device__ int    g_deg[N_MAX];
__device__ int    g_off[N_MAX + 1];
__device__ int    g_csr[T_MAX];
__device__ int    g_bsum[NBLK_SCAN_MAX];
__device__ int    g_is64;

// ---------------- f32x2 packed helpers ----------------
__device__ __forceinline__ unsigned long long pk2(float a, float b) {
    unsigned long long r;
    asm("mov.b64 %0, {%1, %2};" : "=l"(r) : "f"(a), "f"(b));
    return r;
}
__device__ __forceinline__ void fma2(unsigned long long& d, unsigned long long a,
                                     unsigned long long b) {
    asm("fma.rn.f32x2 %0, %1, %2, %0;" : "+l"(d) : "l"(a), "l"(b));
}
__device__ __forceinline__ float2 up2(unsigned long long v) {
    float2 r;
    asm("mov.b64 {%0, %1}, %2;" : "=f"(r.x), "=f"(r.y) : "l"(v));
    return r;
}

// ---------------- init: deg=1 + dtype detect (block 0) ----------------
__global__ void k_init(const unsigned int* __restrict__ w, int N) {
    int i = blockIdx.x * blockDim.x + threadIdx.x;
    if (i < N) g_deg[i] = 1;  // self loop
    if (blockIdx.x == 0) {
        __shared__ int cnt;
        if (threadIdx.x == 0) cnt = 0;
        __syncthreads();
        int z = 0;
        for (int j = threadIdx.x; j < 2048; j += blockDim.x)
            if (w[2 * j + 1] == 0u) z++;
        atomicAdd(&cnt, z);
        __syncthreads();
        if (threadIdx.x == 0) g_is64 = (cnt > 1024) ? 1 : 0;
    }
}

// decode + degree count; atomic return = slot rank (atomic-free scatter later)
__global__ void k_decode_deg(const void* __restrict__ ei, int E) {
    int e = blockIdx.x * blockDim.x + threadIdx.x;
    if (e >= E) return;
    int s, d;
    if (g_is64) {
        const long long* p = (const long long*)ei;
        s = (int)p[e];
        d = (int)p[e + E];
    } else {
        const int* p = (const int*)ei;
        s = p[e];
        d = p[e + E];
    }
    g_src[e] = s;
    int r = atomicAdd(&g_deg[d], 1);  // >=1 (self loop slot 0)
    g_dr[e] = ((unsigned long long)(unsigned)r << 32) | (unsigned)d;
}

// ---------------- scan (warp-shuffle) ----------------
__global__ void k_scan1(int N) {
    __shared__ int wsum[32];
    int i = blockIdx.x * SCAN_B + threadIdx.x;
    int v = (i < N) ? g_deg[i] : 0;
    int lane = threadIdx.x & 31, wid = threadIdx.x >> 5;
    int s = v;
#pragma unroll
    for (int o = 1; o < 32; o <<= 1) {
        int t = __shfl_up_sync(0xffffffffu, s, o);
        if (lane >= o) s += t;
    }
    if (lane == 31) wsum[wid] = s;
    __syncthreads();
    if (wid == 0) {
        int ws = wsum[lane];
#pragma unroll
        for (int o = 1; o < 32; o <<= 1) {
            int t = __shfl_up_sync(0xffffffffu, ws, o);
            if (lane >= o) ws += t;
        }
        wsum[lane] = ws;
    }
    __syncthreads();
    int base = (wid > 0) ? wsum[wid - 1] : 0;
    if (i < N) g_off[i] = base + s - v;  // block-local exclusive
    if (threadIdx.x == 0) g_bsum[blockIdx.x] = wsum[31];
}

// parallel scan over block sums (nblk <= 128)
__global__ void k_scan2(int nblk, int N) {
    __shared__ int ws[4];
    int tid = threadIdx.x;  // 128 threads
    int v = (tid < nblk) ? g_bsum[tid] : 0;
    int lane = tid & 31, w = tid >> 5;
    int s = v;
#pragma unroll
    for (int o = 1; o < 32; o <<= 1) {
        int t = __shfl_up_sync(0xffffffffu, s, o);
        if (lane >= o) s += t;
    }
    if (lane == 31) ws[w] = s;
    __syncthreads();
    int base = 0;
#pragma unroll
    for (int j = 0; j < 4; j++)
        if (j < w) base += ws[j];
    if (tid < nblk) g_bsum[tid] = base + s - v;  // exclusive
    if (tid == nblk - 1) g_off[N] = base + s;
}

// finalize offsets + self-loop scatter fused
__global__ void k_scan3(int N) {
    int i = blockIdx.x * blockDim.x + threadIdx.x;
    if (i < N) {
        int o = g_off[i] + g_bsum[i / SCAN_B];
        g_off[i] = o;
        g_csr[o] = i;  // self loop slot 0
    }
}
// atomic-free scatter using precomputed ranks
__global__ void k_scat_edge(int E) {
    int e = blockIdx.x * blockDim.x + threadIdx.x;
    if (e >= E) return;
    unsigned long long dr = g_dr[e];
    int d = (int)(unsigned)dr;
    int r = (int)(dr >> 32);
    g_csr[__ldg(&g_off[d]) + r] = g_src[e];
}

// ---------------- GEMM1 + fused att dots ----------------------------------
// h1 kept in registers; stores ONLY fp16 copy + att src/dst dots (fp32).
#define SXI(r, kq) ((r) * 128 + ((((kq) ^ ((r) & 7))) << 2))

__global__ void __launch_bounds__(128) k_gemm1(const float* __restrict__ x,
                                               const float* __restrict__ W,
                                               const float* __restrict__ att_s,
                                               const float* __restrict__ att_d,
                                               int N) {
    extern __shared__ float smem[];
    float* sW = smem;           // 128*64
    float* sX = smem + 8192;    // 128*128 swizzled
    float* sAs = smem + 24576;  // 64
    float* sAd = smem + 24640;  // 64
    int tid = threadIdx.x;

    const float4* W4 = (const float4*)W;
    float4* sW4 = (float4*)sW;
#pragma unroll
    for (int i = tid; i < 2048; i += 128) sW4[i] = W4[i];
    if (tid < 64) {
        sAs[tid] = att_s[tid];
        sAd[tid] = att_d[tid];
    }

    int rowbase = blockIdx.x * 128;
    const float4* x4 = (const float4*)x;
#pragma unroll
    for (int idx = tid; idx < 4096; idx += 128) {
        int r = idx >> 5, kq = idx & 31;
        int row = rowbase + r;
        float4 v = make_float4(0.f, 0.f, 0.f, 0.f);
        if (row < N) v = x4[(size_t)row * 32 + kq];
        *(float4*)&sX[SXI(r, kq)] = v;
    }
    __syncthreads();

    int rowthr = tid >> 3;  // 0..15
    int colthr = tid & 7;   // 0..7
    int c0 = colthr * 4;

    unsigned long long acc[8][4];
#pragma unroll
    for (int i = 0; i < 8; i++)
#pragma unroll
        for (int j = 0; j < 4; j++) acc[i][j] = 0ULL;

#pragma unroll 4
    for (int kq = 0; kq < 32; kq++) {
        float4 xq[8];
#pragma unroll
        for (int i = 0; i < 8; i++) xq[i] = *(const float4*)&sX[SXI(rowthr + 16 * i, kq)];
#pragma unroll
        for (int kk = 0; kk < 4; kk++) {
            int k = kq * 4 + kk;
            float4 wa = *(const float4*)&sW[k * 64 + c0];
            float4 wb = *(const float4*)&sW[k * 64 + c0 + 32];
            unsigned long long w0 = pk2(wa.x, wa.y), w1 = pk2(wa.z, wa.w);
            unsigned long long w2 = pk2(wb.x, wb.y), w3 = pk2(wb.z, wb.w);
#pragma unroll
            for (int i = 0; i < 8; i++) {
                float xv = ((const float*)&xq[i])[kk];
                unsigned long long xd = pk2(xv, xv);
                fma2(acc[i][0], xd, w0);
                fma2(acc[i][1], xd, w1);
                fma2(acc[i][2], xd, w2);
                fma2(acc[i][3], xd, w3);
            }
        }
    }

    // epilogue: fp16 store + fused attention dots (pair lanes tid, tid^1)
    float as0 = sAs[c0], as1v = sAs[c0 + 1], as2v = sAs[c0 + 2], as3 = sAs[c0 + 3];
    float asH0 = sAs[c0 + 32], asH1 = sAs[c0 + 33], asH2 = sAs[c0 + 34], asH3 = sAs[c0 + 35];
    float ad0 = sAd[c0], ad1v = sAd[c0 + 1], ad2v = sAd[c0 + 2], ad3 = sAd[c0 + 3];
    float adH0 = sAd[c0 + 32], adH1 = sAd[c0 + 33], adH2 = sAd[c0 + 34], adH3 = sAd[c0 + 35];
    int hl = c0 >> 3;  // valid on even lanes

#pragma unroll
    for (int i = 0; i < 8; i++) {
        int row = rowbase + rowthr + 16 * i;
        bool ok = (row < N);
        float2 p0 = up2(acc[i][0]), p1 = up2(acc[i][1]);
        float2 p2 = up2(acc[i][2]), p3 = up2(acc[i][3]);
        if (ok) {
            __half2 h0 = __floats2half2_rn(p0.x, p0.y);
            __half2 h1v = __floats2half2_rn(p1.x, p1.y);
            __half2 h2v = __floats2half2_rn(p2.x, p2.y);
            __half2 h3 = __floats2half2_rn(p3.x, p3.y);
            uint2 u0, u1;
            u0.x = *(unsigned*)&h0;  u0.y = *(unsigned*)&h1v;
            u1.x = *(unsigned*)&h2v; u1.y = *(unsigned*)&h3;
            *(uint2*)&g_h1h[(size_t)row * 64 + c0] = u0;
            *(uint2*)&g_h1h[(size_t)row * 64 + c0 + 32] = u1;
        }
        float sl = p0.x * as0 + p0.y * as1v + p1.x * as2v + p1.y * as3;
        float sh = p2.x * asH0 + p2.y * asH1 + p3.x * asH2 + p3.y * asH3;
        float dl = p0.x * ad0 + p0.y * ad1v + p1.x * ad2v + p1.y * ad3;
        float dh = p2.x * adH0 + p2.y * adH1 + p3.x * adH2 + p3.y * adH3;
        sl += __shfl_xor_sync(0xffffffffu, sl, 1);
        sh += __shfl_xor_sync(0xffffffffu, sh, 1);
        dl += __shfl_xor_sync(0xffffffffu, dl, 1);
        dh += __shfl_xor_sync(0xffffffffu, dh, 1);
        if (ok && !(tid & 1)) {
            g_as1[row * 8 + hl] = sl;
            g_as1[row * 8 + hl + 4] = sh;
            g_ad1[row * 8 + hl] = dl;
            g_ad1[row * 8 + hl + 4] = dh;
        }
    }
}

// ---------------- aggregate layer 1: warp/node, 2 edges x 16 lanes, fp16 --
__global__ void k_agg1(const float* __restrict__ b1, int N) {
    int warp = (blockIdx.x * blockDim.x + threadIdx.x) >> 5;
    if (warp >= N) return;
    int lane = threadIdx.x & 31;
    int sub = lane >> 4;       // 0/1 edge slot
    int q = lane & 15;         // channel quad
    int c0 = q * 4;
    int head = q >> 1;
    int n = warp;
    float ad = g_ad1[n * 8 + head];
    int beg = g_off[n], end = g_off[n + 1];
    float a0 = 0.f, a1 = 0.f, a2 = 0.f, a3 = 0.f, den = 0.f;
    for (int e = beg + sub; e < end; e += 2) {
        int src = __ldg(&g_csr[e]);
        float as = __ldg(&g_as1[src * 8 + head]);
        float a = as + ad;
        a = (a > 0.f) ? a : 0.2f * a;
        float ex = __expf(a);
        den += ex;
        uint2 hv = *(const uint2*)&g_h1h[(size_t)src * 64 + c0];
        float2 p0 = __half22float2(*(__half2*)&hv.x);
        float2 p1 = __half22float2(*(__half2*)&hv.y);
        a0 = fmaf(ex, p0.x, a0);
        a1 = fmaf(ex, p0.y, a1);
        a2 = fmaf(ex, p1.x, a2);
        a3 = fmaf(ex, p1.y, a3);
    }
    a0 += __shfl_xor_sync(0xffffffffu, a0, 16);
    a1 += __shfl_xor_sync(0xffffffffu, a1, 16);
    a2 += __shfl_xor_sync(0xffffffffu, a2, 16);
    a3 += __shfl_xor_sync(0xffffffffu, a3, 16);
    den += __shfl_xor_sync(0xffffffffu, den, 16);
    if (sub == 0) {
        float inv = 1.f / (den + 1e-16f);
        float o0 = a0 * inv + b1[c0];
        float o1 = a1 * inv + b1[c0 + 1];
        float o2 = a2 * inv + b1[c0 + 2];
        float o3 = a3 * inv + b1[c0 + 3];
        o0 = (o0 > 0.f) ? o0 : (__expf(o0) - 1.f);
        o1 = (o1 > 0.f) ? o1 : (__expf(o1) - 1.f);
        o2 = (o2 > 0.f) ? o2 : (__expf(o2) - 1.f);
        o3 = (o3 > 0.f) ? o3 : (__expf(o3) - 1.f);
        *(float4*)&g_hmid[(size_t)n * 64 + c0] = make_float4(o0, o1, o2, o3);
    }
}

// ---------------- GEMM2 + att dots layer 2 (smem staged) ------------------
__global__ void k_gemm2(const float* __restrict__ W2,
                        const float* __restrict__ att_s,
                        const float* __restrict__ att_d, int N) {
    __shared__ float sW[64 * 16];
    __shared__ float sH[16 * 64];
    __shared__ float sAs[16], sAd[16];
    int tid = threadIdx.x;
    ((float4*)sW)[tid] = ((const float4*)W2)[tid];
    if (tid < 16) {
        sAs[tid] = att_s[tid];
        sAd[tid] = att_d[tid];
    }
    int base = blockIdx.x * 16;
    {
        int r = tid >> 4, kq = tid & 15;
        int node = base + r;
        float4 v = make_float4(0.f, 0.f, 0.f, 0.f);
        if (node < N) v = *(const float4*)&g_hmid[(size_t)node * 64 + kq * 4];
        *(float4*)&sH[r * 64 + kq * 4] = v;
    }
    __syncthreads();

    int nl = tid >> 4, c = tid & 15;
    int node = base + nl;
    float acc = 0.f;
#pragma unroll
    for (int kq = 0; kq < 16; kq++) {
        float4 h = *(const float4*)&sH[nl * 64 + kq * 4];
        acc = fmaf(h.x, sW[(kq * 4 + 0) * 16 + c], acc);
        acc = fmaf(h.y, sW[(kq * 4 + 1) * 16 + c], acc);
        acc = fmaf(h.z, sW[(kq * 4 + 2) * 16 + c], acc);
        acc = fmaf(h.w, sW[(kq * 4 + 3) * 16 + c], acc);
    }
    float p = acc * sAs[c], q = acc * sAd[c];
#pragma unroll
    for (int o = 8; o >= 1; o >>= 1) {
        p += __shfl_xor_sync(0xffffffffu, p, o);
        q += __shfl_xor_sync(0xffffffffu, q, o);
    }
    if (node < N) {
        g_h2[node * 16 + c] = acc;
        if (c == 0) {
            g_as2[node] = p;
            g_ad2[node] = q;
        }
    }
}

// ---------------- aggregate layer 2 + log_softmax: 4 edges x 8 lanes ------
__global__ void k_agg2(const float* __restrict__ b2, float* __restrict__ out,
                       int N) {
    int warp = (blockIdx.x * blockDim.x + threadIdx.x) >> 5;
    if (warp >= N) return;
    int lane = threadIdx.x & 31;
    int sub = lane >> 3;  // 0..3 edge slot
    int cg = lane & 7;
    int c0 = cg * 2;
    int n = warp;
    float ad = g_ad2[n];
    int beg = g_off[n], end = g_off[n + 1];
    float ax = 0.f, ay = 0.f, den = 0.f;
    for (int e = beg + sub; e < end; e += 4) {
        int src = __ldg(&g_csr[e]);
        float as = __ldg(&g_as2[src]);
        float a = as + ad;
        a = (a > 0.f) ? a : 0.2f * a;
        float ex = __expf(a);
        den += ex;
        float2 hv = *(const float2*)&g_h2[src * 16 + c0];
        ax = fmaf(ex, hv.x, ax);
        ay = fmaf(ex, hv.y, ay);
    }
    ax += __shfl_xor_sync(0xffffffffu, ax, 8);
    ax += __shfl_xor_sync(0xffffffffu, ax, 16);
    ay += __shfl_xor_sync(0xffffffffu, ay, 8);
    ay += __shfl_xor_sync(0xffffffffu, ay, 16);
    den += __shfl_xor_sync(0xffffffffu, den, 8);
    den += __shfl_xor_sync(0xffffffffu, den, 16);
    float inv = 1.f / (den + 1e-16f);
    float v0 = ax * inv + b2[c0];
    float v1 = ay * inv + b2[c0 + 1];
    float m = fmaxf(v0, v1);
#pragma unroll
    for (int o = 4; o >= 1; o >>= 1) m = fmaxf(m, __shfl_xor_sync(0xffffffffu, m, o));
    float s = __expf(v0 - m) + __expf(v1 - m);
#pragma unroll
    for (int o = 4; o >= 1; o >>= 1) s += __shfl_xor_sync(0xffffffffu, s, o);
    float ls = __logf(s);
    if (sub == 0) {
        out[n * 16 + c0] = v0 - m - ls;
        out[n * 16 + c0 + 1] = v1 - m - ls;
    }
}

// ---------------------------------------------------------------------------
extern "C" void kernel_launch(void* const* d_in, const int* in_sizes, int n_in,
                              void* d_out, int out_size) {
    const float* x        = (const float*)d_in[0];
    const void*  ei       = d_in[1];
    const float* W1       = (const float*)d_in[2];
    const float* b1       = (const float*)d_in[3];
    const float* att_src1 = (const float*)d_in[4];
    const float* att_dst1 = (const float*)d_in[5];
    const float* W2       = (const float*)d_in[6];
    const float* b2       = (const float*)d_in[7];
    const float* att_src2 = (const float*)d_in[8];
    const float* att_dst2 = (const float*)d_in[9];
    float* out = (float*)d_out;

    int N = in_sizes[0] / 128;
    int E = in_sizes[1] / 2;
    if (N > N_MAX) N = N_MAX;
    if (E > E_MAX) E = E_MAX;

    int gE = (E + 255) / 256;
    int gN = (N + 255) / 256;
    int nblkScan = (N + SCAN_B - 1) / SCAN_B;

    k_init<<<gN, 256>>>((const unsigned int*)ei, N);
    k_decode_deg<<<gE, 256>>>(ei, E);
    k_scan1<<<nblkScan, SCAN_B>>>(N);
    k_scan2<<<1, 128>>>(nblkScan, N);
    k_scan3<<<gN, 256>>>(N);
    k_scat_edge<<<gE, 256>>>(E);

    (void)cudaFuncSetAttribute(k_gemm1,
                               cudaFuncAttributeMaxDynamicSharedMemorySize, 99328);
    k_gemm1<<<(N + 127) / 128, 128, 99328>>>(x, W1, att_src1, att_dst1, N);
    k_agg1<<<(N * 32 + 255) / 256, 256>>>(b1, N);

    k_gemm2<<<(N + 15) / 16, 256>>>(W2, att_src2, att_dst2, N);
    k_agg2<<<(N * 32 + 255) / 256, 256>>>(b2, out, N);
}